// round 10
// baseline (speedup 1.0000x reference)
#include <cuda_runtime.h>
#include <math.h>

// Problem constants
#define BSZ   4
#define TT    2048
#define CC    2048
#define NH    16
#define NKV   4
#define HDIM  128
#define MROWS (BSZ * TT)       // 8192
#define KVC   (NKV * HDIM)     // 512

// Scratch (device globals: allocation is forbidden)
__device__ float g_Q[(size_t)MROWS * CC];    // 64 MB
__device__ float g_K[(size_t)MROWS * KVC];   // 16 MB
__device__ float g_V[(size_t)MROWS * KVC];   // 16 MB
__device__ float g_Y[(size_t)MROWS * CC];    // 64 MB

// ---------------------------------------------------------------------------
// SGEMM: C[M,N] = A[M,K] @ B[K,N], all row-major fp32.
// 128x128 block tile, BK=8, 256 threads, 8x8 per-thread microtile.
// Requires M%128==0, N%128==0, K%8==0 (true for all our shapes).
// ---------------------------------------------------------------------------
__global__ void __launch_bounds__(256) sgemm128(const float* __restrict__ A,
                                                const float* __restrict__ B,
                                                float* __restrict__ Cm,
                                                int N, int K) {
    __shared__ float As[8][128];
    __shared__ float Bs[8][132];

    const int tid = threadIdx.x;
    const int bm  = blockIdx.y * 128;
    const int bn  = blockIdx.x * 128;

    const int tx = tid & 15;   // 0..15 col group
    const int ty = tid >> 4;   // 0..15 row group

    // A tile load mapping: one float4 per thread per k-step
    const int arow = tid >> 1;
    const int acol = (tid & 1) * 4;
    // B tile load mapping
    const int brow = tid >> 5;
    const int bcol = (tid & 31) * 4;

    const float* Aptr = A + (size_t)(bm + arow) * K + acol;
    const float* Bptr = B + (size_t)brow * N + bn + bcol;

    float acc[8][8];
#pragma unroll
    for (int i = 0; i < 8; i++)
#pragma unroll
        for (int j = 0; j < 8; j++) acc[i][j] = 0.f;

    for (int k0 = 0; k0 < K; k0 += 8) {
        float4 av = *(const float4*)(Aptr + k0);
        float4 bv = *(const float4*)(Bptr + (size_t)k0 * N);
        As[acol + 0][arow] = av.x;
        As[acol + 1][arow] = av.y;
        As[acol + 2][arow] = av.z;
        As[acol + 3][arow] = av.w;
        *(float4*)&Bs[brow][bcol] = bv;
        __syncthreads();

#pragma unroll
        for (int kk = 0; kk < 8; kk++) {
            float a[8], b[8];
            *(float4*)&a[0] = *(const float4*)&As[kk][ty * 8];
            *(float4*)&a[4] = *(const float4*)&As[kk][ty * 8 + 4];
            *(float4*)&b[0] = *(const float4*)&Bs[kk][tx * 8];
            *(float4*)&b[4] = *(const float4*)&Bs[kk][tx * 8 + 4];
#pragma unroll
            for (int i = 0; i < 8; i++)
#pragma unroll
                for (int j = 0; j < 8; j++)
                    acc[i][j] += a[i] * b[j];
        }
        __syncthreads();
    }

#pragma unroll
    for (int i = 0; i < 8; i++) {
        size_t r = (size_t)(bm + ty * 8 + i);
        float4 v0 = make_float4(acc[i][0], acc[i][1], acc[i][2], acc[i][3]);
        float4 v1 = make_float4(acc[i][4], acc[i][5], acc[i][6], acc[i][7]);
        *(float4*)&Cm[r * N + bn + tx * 8]     = v0;
        *(float4*)&Cm[r * N + bn + tx * 8 + 4] = v1;
    }
}

// ---------------------------------------------------------------------------
// RoPE on Q [MROWS, NH, HDIM] and K [MROWS, NKV, HDIM].
// freqs_cis: [T, 64, 2] = (cos, sin) pairs.
// ---------------------------------------------------------------------------
__global__ void rope_kernel(float* __restrict__ Qb, float* __restrict__ Kb,
                            const float* __restrict__ fc) {
    int idx = blockIdx.x * blockDim.x + threadIdx.x;
    const int qpairs = MROWS * NH * (HDIM / 2);   // 8388608
    const int kpairs = MROWS * NKV * (HDIM / 2);  // 2097152
    if (idx < qpairs) {
        int p   = idx & 63;
        int h   = (idx >> 6) & (NH - 1);
        int row = idx >> 10;           // / (64*16)
        int t   = row & (TT - 1);
        float2 cs = ((const float2*)fc)[t * 64 + p];
        float2* ptr = (float2*)(Qb + (size_t)row * CC + h * HDIM) + p;
        float2 v = *ptr;
        *ptr = make_float2(v.x * cs.x - v.y * cs.y, v.x * cs.y + v.y * cs.x);
    } else if (idx < qpairs + kpairs) {
        int j   = idx - qpairs;
        int p   = j & 63;
        int h   = (j >> 6) & (NKV - 1);
        int row = j >> 8;              // / (64*4)
        int t   = row & (TT - 1);
        float2 cs = ((const float2*)fc)[t * 64 + p];
        float2* ptr = (float2*)(Kb + (size_t)row * KVC + h * HDIM) + p;
        float2 v = *ptr;
        *ptr = make_float2(v.x * cs.x - v.y * cs.y, v.x * cs.y + v.y * cs.x);
    }
}

// ---------------------------------------------------------------------------
// Flash attention (fp32, causal, GQA). BM=BN=64, HD=128, 256 threads.
// grid: (T/64, B*NH). Each thread: 4x4 S microtile, 4x8 O microtile.
// Row reductions via 16-lane shfl (lanes [0,16) / [16,32) of each warp).
// ---------------------------------------------------------------------------
#define FL_QS 0                      // QsT [128][68]
#define FL_KS (128 * 68)             // KsT [128][68]
#define FL_VS (FL_KS + 128 * 68)     // Vs  [64][132]
#define FL_PS (FL_VS + 64 * 132)     // Ps  [64][68]
#define FL_SMEM_FLOATS (FL_PS + 64 * 68)
#define FL_SMEM_BYTES  (FL_SMEM_FLOATS * 4)   // 120832

__global__ void __launch_bounds__(256) flash_kernel(const float* __restrict__ Q,
                                                    const float* __restrict__ Kb,
                                                    const float* __restrict__ Vb,
                                                    float* __restrict__ Y) {
    extern __shared__ float sm[];
    float* QsT = sm + FL_QS;
    float* KsT = sm + FL_KS;
    float* Vs  = sm + FL_VS;
    float* Ps  = sm + FL_PS;

    const int tid = threadIdx.x;
    const int qb  = blockIdx.x;            // query tile index
    const int bh  = blockIdx.y;
    const int b   = bh / NH;
    const int h   = bh % NH;
    const int g   = h >> 2;                // kv head (N_REP = 4)

    const float* qsrc0 = Q  + (size_t)b * TT * CC  + (size_t)h * HDIM;
    const float* ksrc0 = Kb + (size_t)b * TT * KVC + (size_t)g * HDIM;
    const float* vsrc0 = Vb + (size_t)b * TT * KVC + (size_t)g * HDIM;

    // Load Q tile transposed: QsT[d][r]
    {
        int r = tid >> 2, f = tid & 3;
        const float* src = qsrc0 + (size_t)(qb * 64 + r) * CC;
#pragma unroll
        for (int q = 0; q < 8; q++) {
            int d = (f * 8 + q) * 4;
            float4 v = *(const float4*)(src + d);
            QsT[(d + 0) * 68 + r] = v.x;
            QsT[(d + 1) * 68 + r] = v.y;
            QsT[(d + 2) * 68 + r] = v.z;
            QsT[(d + 3) * 68 + r] = v.w;
        }
    }

    const int rg = tid >> 4;     // 0..15
    const int cg = tid & 15;     // 0..15
    const int r0 = rg * 4;
    const int c0 = cg * 4;
    const int oc0 = cg * 8;

    float m_i[4], l_i[4], o[4][8];
#pragma unroll
    for (int i = 0; i < 4; i++) {
        m_i[i] = -1e30f; l_i[i] = 0.f;
#pragma unroll
        for (int j = 0; j < 8; j++) o[i][j] = 0.f;
    }

    const float scale = 0.08838834764831845f;  // 1/sqrt(128)
    const int ntiles = qb + 1;

    for (int kt = 0; kt < ntiles; kt++) {
        __syncthreads();  // protect K/V/P from previous iteration's readers
        // Load K tile (transposed) and V tile (row-major)
        {
            int r = tid >> 2, f = tid & 3;
            const float* ks = ksrc0 + (size_t)(kt * 64 + r) * KVC;
            const float* vs = vsrc0 + (size_t)(kt * 64 + r) * KVC;
#pragma unroll
            for (int q = 0; q < 8; q++) {
                int d = (f * 8 + q) * 4;
                float4 kv = *(const float4*)(ks + d);
                KsT[(d + 0) * 68 + r] = kv.x;
                KsT[(d + 1) * 68 + r] = kv.y;
                KsT[(d + 2) * 68 + r] = kv.z;
                KsT[(d + 3) * 68 + r] = kv.w;
                *(float4*)&Vs[r * 132 + d] = *(const float4*)(vs + d);
            }
        }
        __syncthreads();

        // S = Q @ K^T (4x4 per thread)
        float s[4][4];
#pragma unroll
        for (int i = 0; i < 4; i++)
#pragma unroll
            for (int j = 0; j < 4; j++) s[i][j] = 0.f;

#pragma unroll 4
        for (int d = 0; d < HDIM; d++) {
            float4 a4 = *(const float4*)&QsT[d * 68 + r0];
            float4 b4 = *(const float4*)&KsT[d * 68 + c0];
            float av[4] = {a4.x, a4.y, a4.z, a4.w};
            float bv[4] = {b4.x, b4.y, b4.z, b4.w};
#pragma unroll
            for (int i = 0; i < 4; i++)
#pragma unroll
                for (int j = 0; j < 4; j++)
                    s[i][j] += av[i] * bv[j];
        }

        // Scale + causal mask
        const int qrow0 = qb * 64 + r0;
        const int kcol0 = kt * 64 + c0;
#pragma unroll
        for (int i = 0; i < 4; i++)
#pragma unroll
            for (int j = 0; j < 4; j++) {
                s[i][j] *= scale;
                if (kcol0 + j > qrow0 + i) s[i][j] = -1e30f;
            }

        // Online softmax update (per row, reduce across 16 col-lanes)
#pragma unroll
        for (int i = 0; i < 4; i++) {
            float mx = fmaxf(fmaxf(s[i][0], s[i][1]), fmaxf(s[i][2], s[i][3]));
#pragma unroll
            for (int off = 1; off < 16; off <<= 1)
                mx = fmaxf(mx, __shfl_xor_sync(0xffffffffu, mx, off));
            float m_new = fmaxf(m_i[i], mx);
            float corr  = __expf(m_i[i] - m_new);
            float psum = 0.f;
#pragma unroll
            for (int j = 0; j < 4; j++) {
                float p = __expf(s[i][j] - m_new);
                s[i][j] = p;
                psum += p;
            }
#pragma unroll
            for (int off = 1; off < 16; off <<= 1)
                psum += __shfl_xor_sync(0xffffffffu, psum, off);
            l_i[i] = l_i[i] * corr + psum;
            m_i[i] = m_new;
#pragma unroll
            for (int j = 0; j < 8; j++) o[i][j] *= corr;
        }

        // Stage P to smem for the PV GEMM
#pragma unroll
        for (int i = 0; i < 4; i++)
#pragma unroll
            for (int j = 0; j < 4; j++)
                Ps[(r0 + i) * 68 + c0 + j] = s[i][j];
        __syncthreads();

        // O += P @ V  (4 rows x 8 cols per thread)
#pragma unroll 4
        for (int j = 0; j < 64; j++) {
            float p0 = Ps[(r0 + 0) * 68 + j];
            float p1 = Ps[(r0 + 1) * 68 + j];
            float p2 = Ps[(r0 + 2) * 68 + j];
            float p3 = Ps[(r0 + 3) * 68 + j];
            float4 v0 = *(const float4*)&Vs[j * 132 + oc0];
            float4 v1 = *(const float4*)&Vs[j * 132 + oc0 + 4];
            float vv[8] = {v0.x, v0.y, v0.z, v0.w, v1.x, v1.y, v1.z, v1.w};
#pragma unroll
            for (int c = 0; c < 8; c++) {
                o[0][c] += p0 * vv[c];
                o[1][c] += p1 * vv[c];
                o[2][c] += p2 * vv[c];
                o[3][c] += p3 * vv[c];
            }
        }
    }

    // Epilogue: normalize and write Y[b, t, h*HD + oc0 .. +7]
#pragma unroll
    for (int i = 0; i < 4; i++) {
        float inv = 1.f / l_i[i];
        size_t row = (size_t)b * TT + (size_t)(qb * 64 + r0 + i);
        float* dst = Y + row * CC + h * HDIM + oc0;
        float4 w0 = make_float4(o[i][0] * inv, o[i][1] * inv,
                                o[i][2] * inv, o[i][3] * inv);
        float4 w1 = make_float4(o[i][4] * inv, o[i][5] * inv,
                                o[i][6] * inv, o[i][7] * inv);
        *(float4*)dst       = w0;
        *(float4*)(dst + 4) = w1;
    }
}

// ---------------------------------------------------------------------------
extern "C" void kernel_launch(void* const* d_in, const int* in_sizes, int n_in,
                              void* d_out, int out_size) {
    (void)in_sizes; (void)n_in; (void)out_size;
    const float* x  = (const float*)d_in[0];
    const float* fc = (const float*)d_in[1];
    const float* wq = (const float*)d_in[2];
    const float* wk = (const float*)d_in[3];
    const float* wv = (const float*)d_in[4];
    const float* wo = (const float*)d_in[5];
    float* out = (float*)d_out;

    float *Qp, *Kp, *Vp, *Yp;
    cudaGetSymbolAddress((void**)&Qp, g_Q);
    cudaGetSymbolAddress((void**)&Kp, g_K);
    cudaGetSymbolAddress((void**)&Vp, g_V);
    cudaGetSymbolAddress((void**)&Yp, g_Y);

    dim3 blk(256);

    // QKV projections
    sgemm128<<<dim3(CC / 128,  MROWS / 128), blk>>>(x, wq, Qp, CC,  CC);
    sgemm128<<<dim3(KVC / 128, MROWS / 128), blk>>>(x, wk, Kp, KVC, CC);
    sgemm128<<<dim3(KVC / 128, MROWS / 128), blk>>>(x, wv, Vp, KVC, CC);

    // RoPE on Q and K
    int total_pairs = MROWS * NH * (HDIM / 2) + MROWS * NKV * (HDIM / 2);
    rope_kernel<<<(total_pairs + 255) / 256, 256>>>(Qp, Kp, fc);

    // Flash attention
    cudaFuncSetAttribute(flash_kernel, cudaFuncAttributeMaxDynamicSharedMemorySize,
                         FL_SMEM_BYTES);
    flash_kernel<<<dim3(TT / 64, BSZ * NH), blk, FL_SMEM_BYTES>>>(Qp, Kp, Vp, Yp);

    // Output projection
    sgemm128<<<dim3(CC / 128, MROWS / 128), blk>>>(Yp, wo, out, CC, CC);
}

// round 13
// speedup vs baseline: 1.5828x; 1.5828x over previous
#include <cuda_runtime.h>
#include <cuda_bf16.h>
#include <math.h>
#include <stdint.h>

// Problem constants
#define BSZ   4
#define TT    2048
#define CC    2048
#define NH    16
#define NKV   4
#define HDIM  128
#define MROWS (BSZ * TT)       // 8192
#define KVC   (NKV * HDIM)     // 512

// fp32 scratch
__device__ float g_Q[(size_t)MROWS * CC];    // 64 MB
__device__ float g_K[(size_t)MROWS * KVC];   // 16 MB
__device__ float g_V[(size_t)MROWS * KVC];   // 16 MB
__device__ float g_Y[(size_t)MROWS * CC];    // 64 MB

// bf16 split scratch
__device__ __nv_bfloat16 g_xh[(size_t)MROWS * CC];
__device__ __nv_bfloat16 g_xl[(size_t)MROWS * CC];
__device__ __nv_bfloat16 g_yh[(size_t)MROWS * CC];
__device__ __nv_bfloat16 g_yl[(size_t)MROWS * CC];
__device__ __nv_bfloat16 g_wqh[(size_t)CC * CC];   // transposed [N][K]
__device__ __nv_bfloat16 g_wql[(size_t)CC * CC];
__device__ __nv_bfloat16 g_wkh[(size_t)KVC * CC];
__device__ __nv_bfloat16 g_wkl[(size_t)KVC * CC];
__device__ __nv_bfloat16 g_wvh[(size_t)KVC * CC];
__device__ __nv_bfloat16 g_wvl[(size_t)KVC * CC];
__device__ __nv_bfloat16 g_woh[(size_t)CC * CC];
__device__ __nv_bfloat16 g_wol[(size_t)CC * CC];

// ---------------------------------------------------------------------------
// Split fp32 -> (hi, lo) bf16, no transpose. n4 = elements/4.
// ---------------------------------------------------------------------------
__global__ void split_kernel(const float* __restrict__ src,
                             __nv_bfloat16* __restrict__ hi,
                             __nv_bfloat16* __restrict__ lo, int n4) {
    int i = blockIdx.x * blockDim.x + threadIdx.x;
    if (i >= n4) return;
    float4 v = ((const float4*)src)[i];
    __nv_bfloat16 h[4], l[4];
    float vv[4] = {v.x, v.y, v.z, v.w};
#pragma unroll
    for (int j = 0; j < 4; j++) {
        h[j] = __float2bfloat16(vv[j]);
        l[j] = __float2bfloat16(vv[j] - __bfloat162float(h[j]));
    }
    *(uint2*)&hi[(size_t)i * 4] = *(uint2*)h;
    *(uint2*)&lo[(size_t)i * 4] = *(uint2*)l;
}

// ---------------------------------------------------------------------------
// Split + transpose: src [K][N] fp32 -> hi/lo [N][K] bf16.
// block (32,8), grid (N/32, K/32).
// ---------------------------------------------------------------------------
__global__ void split_transpose_kernel(const float* __restrict__ src,
                                       __nv_bfloat16* __restrict__ hi,
                                       __nv_bfloat16* __restrict__ lo,
                                       int K, int N) {
    __shared__ float tile[32][33];
    int n0 = blockIdx.x * 32, k0 = blockIdx.y * 32;
    int tx = threadIdx.x, ty = threadIdx.y;
#pragma unroll
    for (int i = 0; i < 32; i += 8)
        tile[ty + i][tx] = src[(size_t)(k0 + ty + i) * N + n0 + tx];
    __syncthreads();
#pragma unroll
    for (int i = 0; i < 32; i += 8) {
        float v = tile[tx][ty + i];
        __nv_bfloat16 h = __float2bfloat16(v);
        __nv_bfloat16 l = __float2bfloat16(v - __bfloat162float(h));
        size_t o = (size_t)(n0 + ty + i) * K + k0 + tx;
        hi[o] = h;
        lo[o] = l;
    }
}

// ---------------------------------------------------------------------------
// bf16-split tensor-core GEMM:
//   C[M,N] (fp32) = (Ah+Al)[M,K] @ (Bh+Bl)^T, B given transposed [N][K].
//   Computes Ah*Bh + Ah*Bl + Al*Bh via mma.sync.m16n8k16 with fp32 accum.
// 128x128x32 tile, 256 threads, warp tile 32x64. M%128==0, N%128==0, K%32==0.
// ---------------------------------------------------------------------------
__device__ __forceinline__ void mma_bf16(float* d, const uint32_t* a,
                                         const uint32_t* b) {
    asm volatile(
        "mma.sync.aligned.m16n8k16.row.col.f32.bf16.bf16.f32 "
        "{%0,%1,%2,%3}, {%4,%5,%6,%7}, {%8,%9}, {%0,%1,%2,%3};\n"
        : "+f"(d[0]), "+f"(d[1]), "+f"(d[2]), "+f"(d[3])
        : "r"(a[0]), "r"(a[1]), "r"(a[2]), "r"(a[3]), "r"(b[0]), "r"(b[1]));
}

#define SSTR 40  // padded smem row stride in bf16 elems (20 banks: conflict-free)

__global__ void __launch_bounds__(256) bgemm128(
    const __nv_bfloat16* __restrict__ Ah, const __nv_bfloat16* __restrict__ Al,
    const __nv_bfloat16* __restrict__ Bh, const __nv_bfloat16* __restrict__ Bl,
    float* __restrict__ Cm, int N, int K) {
    __shared__ __nv_bfloat16 sAh[128 * SSTR];
    __shared__ __nv_bfloat16 sAl[128 * SSTR];
    __shared__ __nv_bfloat16 sBh[128 * SSTR];
    __shared__ __nv_bfloat16 sBl[128 * SSTR];

    const int tid = threadIdx.x;
    const int bm = blockIdx.y * 128;
    const int bn = blockIdx.x * 128;

    // Global tile load mapping: 128 rows x 4 x 16B chunks per matrix,
    // 2 chunks per thread (rows r0 and r0+64).
    const int r0 = tid >> 2;
    const int c0 = (tid & 3) * 8;   // bf16 element offset

    const int wid = tid >> 5, lane = tid & 31;
    const int wm = (wid & 3) * 32;
    const int wn = (wid >> 2) * 64;
    const int fr = lane >> 2;        // 0..7
    const int fc = (lane & 3) * 2;   // 0,2,4,6

    float acc[16][4];
#pragma unroll
    for (int i = 0; i < 16; i++)
#pragma unroll
        for (int j = 0; j < 4; j++) acc[i][j] = 0.f;

    const __nv_bfloat16* pAh0 = Ah + (size_t)(bm + r0) * K + c0;
    const __nv_bfloat16* pAh1 = Ah + (size_t)(bm + r0 + 64) * K + c0;
    const __nv_bfloat16* pAl0 = Al + (size_t)(bm + r0) * K + c0;
    const __nv_bfloat16* pAl1 = Al + (size_t)(bm + r0 + 64) * K + c0;
    const __nv_bfloat16* pBh0 = Bh + (size_t)(bn + r0) * K + c0;
    const __nv_bfloat16* pBh1 = Bh + (size_t)(bn + r0 + 64) * K + c0;
    const __nv_bfloat16* pBl0 = Bl + (size_t)(bn + r0) * K + c0;
    const __nv_bfloat16* pBl1 = Bl + (size_t)(bn + r0 + 64) * K + c0;

    uint4 pa0, pa1, pa2, pa3, pb0, pb1, pb2, pb3;
    // prefetch k0 = 0
    pa0 = *(const uint4*)(pAh0); pa1 = *(const uint4*)(pAh1);
    pa2 = *(const uint4*)(pAl0); pa3 = *(const uint4*)(pAl1);
    pb0 = *(const uint4*)(pBh0); pb1 = *(const uint4*)(pBh1);
    pb2 = *(const uint4*)(pBl0); pb3 = *(const uint4*)(pBl1);

    for (int k0 = 0; k0 < K; k0 += 32) {
        // commit prefetched tile to smem
        *(uint4*)&sAh[r0 * SSTR + c0]        = pa0;
        *(uint4*)&sAh[(r0 + 64) * SSTR + c0] = pa1;
        *(uint4*)&sAl[r0 * SSTR + c0]        = pa2;
        *(uint4*)&sAl[(r0 + 64) * SSTR + c0] = pa3;
        *(uint4*)&sBh[r0 * SSTR + c0]        = pb0;
        *(uint4*)&sBh[(r0 + 64) * SSTR + c0] = pb1;
        *(uint4*)&sBl[r0 * SSTR + c0]        = pb2;
        *(uint4*)&sBl[(r0 + 64) * SSTR + c0] = pb3;
        __syncthreads();

        if (k0 + 32 < K) {
            int kn = k0 + 32;
            pa0 = *(const uint4*)(pAh0 + kn); pa1 = *(const uint4*)(pAh1 + kn);
            pa2 = *(const uint4*)(pAl0 + kn); pa3 = *(const uint4*)(pAl1 + kn);
            pb0 = *(const uint4*)(pBh0 + kn); pb1 = *(const uint4*)(pBh1 + kn);
            pb2 = *(const uint4*)(pBl0 + kn); pb3 = *(const uint4*)(pBl1 + kn);
        }

#pragma unroll
        for (int kk = 0; kk < 2; kk++) {
            const int kb = kk * 16;
            uint32_t ah[2][4], al[2][4];
#pragma unroll
            for (int mi = 0; mi < 2; mi++) {
                int r = wm + mi * 16 + fr;
                ah[mi][0] = *(const uint32_t*)&sAh[r * SSTR + kb + fc];
                ah[mi][1] = *(const uint32_t*)&sAh[(r + 8) * SSTR + kb + fc];
                ah[mi][2] = *(const uint32_t*)&sAh[r * SSTR + kb + fc + 8];
                ah[mi][3] = *(const uint32_t*)&sAh[(r + 8) * SSTR + kb + fc + 8];
                al[mi][0] = *(const uint32_t*)&sAl[r * SSTR + kb + fc];
                al[mi][1] = *(const uint32_t*)&sAl[(r + 8) * SSTR + kb + fc];
                al[mi][2] = *(const uint32_t*)&sAl[r * SSTR + kb + fc + 8];
                al[mi][3] = *(const uint32_t*)&sAl[(r + 8) * SSTR + kb + fc + 8];
            }
#pragma unroll
            for (int ni = 0; ni < 8; ni++) {
                int c = wn + ni * 8 + fr;
                uint32_t bh[2], bl[2];
                bh[0] = *(const uint32_t*)&sBh[c * SSTR + kb + fc];
                bh[1] = *(const uint32_t*)&sBh[c * SSTR + kb + fc + 8];
                bl[0] = *(const uint32_t*)&sBl[c * SSTR + kb + fc];
                bl[1] = *(const uint32_t*)&sBl[c * SSTR + kb + fc + 8];
#pragma unroll
                for (int mi = 0; mi < 2; mi++) {
                    float* d = acc[mi * 8 + ni];
                    mma_bf16(d, ah[mi], bh);   // hi*hi
                    mma_bf16(d, ah[mi], bl);   // hi*lo
                    mma_bf16(d, al[mi], bh);   // lo*hi
                }
            }
        }
        __syncthreads();
    }

    // Writeback
#pragma unroll
    for (int mi = 0; mi < 2; mi++) {
#pragma unroll
        for (int ni = 0; ni < 8; ni++) {
            const float* d = acc[mi * 8 + ni];
            size_t row = (size_t)(bm + wm + mi * 16 + fr);
            int col = bn + wn + ni * 8 + fc;
            *(float2*)&Cm[row * N + col]       = make_float2(d[0], d[1]);
            *(float2*)&Cm[(row + 8) * N + col] = make_float2(d[2], d[3]);
        }
    }
}

// ---------------------------------------------------------------------------
// RoPE on Q [MROWS, NH, HDIM] and K [MROWS, NKV, HDIM] (fp32).
// ---------------------------------------------------------------------------
__global__ void rope_kernel(float* __restrict__ Qb, float* __restrict__ Kb,
                            const float* __restrict__ fc) {
    int idx = blockIdx.x * blockDim.x + threadIdx.x;
    const int qpairs = MROWS * NH * (HDIM / 2);
    const int kpairs = MROWS * NKV * (HDIM / 2);
    if (idx < qpairs) {
        int p   = idx & 63;
        int h   = (idx >> 6) & (NH - 1);
        int row = idx >> 10;
        int t   = row & (TT - 1);
        float2 cs = ((const float2*)fc)[t * 64 + p];
        float2* ptr = (float2*)(Qb + (size_t)row * CC + h * HDIM) + p;
        float2 v = *ptr;
        *ptr = make_float2(v.x * cs.x - v.y * cs.y, v.x * cs.y + v.y * cs.x);
    } else if (idx < qpairs + kpairs) {
        int j   = idx - qpairs;
        int p   = j & 63;
        int h   = (j >> 6) & (NKV - 1);
        int row = j >> 8;
        int t   = row & (TT - 1);
        float2 cs = ((const float2*)fc)[t * 64 + p];
        float2* ptr = (float2*)(Kb + (size_t)row * KVC + h * HDIM) + p;
        float2 v = *ptr;
        *ptr = make_float2(v.x * cs.x - v.y * cs.y, v.x * cs.y + v.y * cs.x);
    }
}

// ---------------------------------------------------------------------------
// Flash attention (fp32, causal, GQA). BM=BN=64, HD=128, 256 threads.
// ---------------------------------------------------------------------------
#define FL_QS 0
#define FL_KS (128 * 68)
#define FL_VS (FL_KS + 128 * 68)
#define FL_PS (FL_VS + 64 * 132)
#define FL_SMEM_FLOATS (FL_PS + 64 * 68)
#define FL_SMEM_BYTES  (FL_SMEM_FLOATS * 4)

__global__ void __launch_bounds__(256) flash_kernel(const float* __restrict__ Q,
                                                    const float* __restrict__ Kb,
                                                    const float* __restrict__ Vb,
                                                    float* __restrict__ Y) {
    extern __shared__ float sm[];
    float* QsT = sm + FL_QS;
    float* KsT = sm + FL_KS;
    float* Vs  = sm + FL_VS;
    float* Ps  = sm + FL_PS;

    const int tid = threadIdx.x;
    const int qb  = blockIdx.x;
    const int bh  = blockIdx.y;
    const int b   = bh / NH;
    const int h   = bh % NH;
    const int g   = h >> 2;

    const float* qsrc0 = Q  + (size_t)b * TT * CC  + (size_t)h * HDIM;
    const float* ksrc0 = Kb + (size_t)b * TT * KVC + (size_t)g * HDIM;
    const float* vsrc0 = Vb + (size_t)b * TT * KVC + (size_t)g * HDIM;

    {
        int r = tid >> 2, f = tid & 3;
        const float* src = qsrc0 + (size_t)(qb * 64 + r) * CC;
#pragma unroll
        for (int q = 0; q < 8; q++) {
            int d = (f * 8 + q) * 4;
            float4 v = *(const float4*)(src + d);
            QsT[(d + 0) * 68 + r] = v.x;
            QsT[(d + 1) * 68 + r] = v.y;
            QsT[(d + 2) * 68 + r] = v.z;
            QsT[(d + 3) * 68 + r] = v.w;
        }
    }

    const int rg = tid >> 4;
    const int cg = tid & 15;
    const int r0 = rg * 4;
    const int c0 = cg * 4;
    const int oc0 = cg * 8;

    float m_i[4], l_i[4], o[4][8];
#pragma unroll
    for (int i = 0; i < 4; i++) {
        m_i[i] = -1e30f; l_i[i] = 0.f;
#pragma unroll
        for (int j = 0; j < 8; j++) o[i][j] = 0.f;
    }

    const float scale = 0.08838834764831845f;
    const int ntiles = qb + 1;

    for (int kt = 0; kt < ntiles; kt++) {
        __syncthreads();
        {
            int r = tid >> 2, f = tid & 3;
            const float* ks = ksrc0 + (size_t)(kt * 64 + r) * KVC;
            const float* vs = vsrc0 + (size_t)(kt * 64 + r) * KVC;
#pragma unroll
            for (int q = 0; q < 8; q++) {
                int d = (f * 8 + q) * 4;
                float4 kv = *(const float4*)(ks + d);
                KsT[(d + 0) * 68 + r] = kv.x;
                KsT[(d + 1) * 68 + r] = kv.y;
                KsT[(d + 2) * 68 + r] = kv.z;
                KsT[(d + 3) * 68 + r] = kv.w;
                *(float4*)&Vs[r * 132 + d] = *(const float4*)(vs + d);
            }
        }
        __syncthreads();

        float s[4][4];
#pragma unroll
        for (int i = 0; i < 4; i++)
#pragma unroll
            for (int j = 0; j < 4; j++) s[i][j] = 0.f;

#pragma unroll 4
        for (int d = 0; d < HDIM; d++) {
            float4 a4 = *(const float4*)&QsT[d * 68 + r0];
            float4 b4 = *(const float4*)&KsT[d * 68 + c0];
            float av[4] = {a4.x, a4.y, a4.z, a4.w};
            float bv[4] = {b4.x, b4.y, b4.z, b4.w};
#pragma unroll
            for (int i = 0; i < 4; i++)
#pragma unroll
                for (int j = 0; j < 4; j++)
                    s[i][j] += av[i] * bv[j];
        }

        const int qrow0 = qb * 64 + r0;
        const int kcol0 = kt * 64 + c0;
#pragma unroll
        for (int i = 0; i < 4; i++)
#pragma unroll
            for (int j = 0; j < 4; j++) {
                s[i][j] *= scale;
                if (kcol0 + j > qrow0 + i) s[i][j] = -1e30f;
            }

#pragma unroll
        for (int i = 0; i < 4; i++) {
            float mx = fmaxf(fmaxf(s[i][0], s[i][1]), fmaxf(s[i][2], s[i][3]));
#pragma unroll
            for (int off = 1; off < 16; off <<= 1)
                mx = fmaxf(mx, __shfl_xor_sync(0xffffffffu, mx, off));
            float m_new = fmaxf(m_i[i], mx);
            float corr  = __expf(m_i[i] - m_new);
            float psum = 0.f;
#pragma unroll
            for (int j = 0; j < 4; j++) {
                float p = __expf(s[i][j] - m_new);
                s[i][j] = p;
                psum += p;
            }
#pragma unroll
            for (int off = 1; off < 16; off <<= 1)
                psum += __shfl_xor_sync(0xffffffffu, psum, off);
            l_i[i] = l_i[i] * corr + psum;
            m_i[i] = m_new;
#pragma unroll
            for (int j = 0; j < 8; j++) o[i][j] *= corr;
        }

#pragma unroll
        for (int i = 0; i < 4; i++)
#pragma unroll
            for (int j = 0; j < 4; j++)
                Ps[(r0 + i) * 68 + c0 + j] = s[i][j];
        __syncthreads();

#pragma unroll 4
        for (int j = 0; j < 64; j++) {
            float p0 = Ps[(r0 + 0) * 68 + j];
            float p1 = Ps[(r0 + 1) * 68 + j];
            float p2 = Ps[(r0 + 2) * 68 + j];
            float p3 = Ps[(r0 + 3) * 68 + j];
            float4 v0 = *(const float4*)&Vs[j * 132 + oc0];
            float4 v1 = *(const float4*)&Vs[j * 132 + oc0 + 4];
            float vv[8] = {v0.x, v0.y, v0.z, v0.w, v1.x, v1.y, v1.z, v1.w};
#pragma unroll
            for (int c = 0; c < 8; c++) {
                o[0][c] += p0 * vv[c];
                o[1][c] += p1 * vv[c];
                o[2][c] += p2 * vv[c];
                o[3][c] += p3 * vv[c];
            }
        }
    }

#pragma unroll
    for (int i = 0; i < 4; i++) {
        float inv = 1.f / l_i[i];
        size_t row = (size_t)b * TT + (size_t)(qb * 64 + r0 + i);
        float* dst = Y + row * CC + h * HDIM + oc0;
        float4 w0 = make_float4(o[i][0] * inv, o[i][1] * inv,
                                o[i][2] * inv, o[i][3] * inv);
        float4 w1 = make_float4(o[i][4] * inv, o[i][5] * inv,
                                o[i][6] * inv, o[i][7] * inv);
        *(float4*)dst       = w0;
        *(float4*)(dst + 4) = w1;
    }
}

// ---------------------------------------------------------------------------
extern "C" void kernel_launch(void* const* d_in, const int* in_sizes, int n_in,
                              void* d_out, int out_size) {
    (void)in_sizes; (void)n_in; (void)out_size;
    const float* x  = (const float*)d_in[0];
    const float* fc = (const float*)d_in[1];
    const float* wq = (const float*)d_in[2];
    const float* wk = (const float*)d_in[3];
    const float* wv = (const float*)d_in[4];
    const float* wo = (const float*)d_in[5];
    float* out = (float*)d_out;

    float *Qp, *Kp, *Vp, *Yp;
    cudaGetSymbolAddress((void**)&Qp, g_Q);
    cudaGetSymbolAddress((void**)&Kp, g_K);
    cudaGetSymbolAddress((void**)&Vp, g_V);
    cudaGetSymbolAddress((void**)&Yp, g_Y);

    __nv_bfloat16 *xh, *xl, *yh, *yl;
    __nv_bfloat16 *wqh, *wql, *wkh, *wkl, *wvh, *wvl, *woh, *wol;
    cudaGetSymbolAddress((void**)&xh,  g_xh);
    cudaGetSymbolAddress((void**)&xl,  g_xl);
    cudaGetSymbolAddress((void**)&yh,  g_yh);
    cudaGetSymbolAddress((void**)&yl,  g_yl);
    cudaGetSymbolAddress((void**)&wqh, g_wqh);
    cudaGetSymbolAddress((void**)&wql, g_wql);
    cudaGetSymbolAddress((void**)&wkh, g_wkh);
    cudaGetSymbolAddress((void**)&wkl, g_wkl);
    cudaGetSymbolAddress((void**)&wvh, g_wvh);
    cudaGetSymbolAddress((void**)&wvl, g_wvl);
    cudaGetSymbolAddress((void**)&woh, g_woh);
    cudaGetSymbolAddress((void**)&wol, g_wol);

    dim3 blk(256);
    dim3 tblk(32, 8);

    // Split inputs / weights (weights transposed to [N][K])
    int xn4 = MROWS * CC / 4;
    split_kernel<<<(xn4 + 255) / 256, blk>>>(x, xh, xl, xn4);
    split_transpose_kernel<<<dim3(CC / 32,  CC / 32), tblk>>>(wq, wqh, wql, CC, CC);
    split_transpose_kernel<<<dim3(KVC / 32, CC / 32), tblk>>>(wk, wkh, wkl, CC, KVC);
    split_transpose_kernel<<<dim3(KVC / 32, CC / 32), tblk>>>(wv, wvh, wvl, CC, KVC);
    split_transpose_kernel<<<dim3(CC / 32,  CC / 32), tblk>>>(wo, woh, wol, CC, CC);

    // QKV projections (tensor cores)
    bgemm128<<<dim3(CC / 128,  MROWS / 128), blk>>>(xh, xl, wqh, wql, Qp, CC,  CC);
    bgemm128<<<dim3(KVC / 128, MROWS / 128), blk>>>(xh, xl, wkh, wkl, Kp, KVC, CC);
    bgemm128<<<dim3(KVC / 128, MROWS / 128), blk>>>(xh, xl, wvh, wvl, Vp, KVC, CC);

    // RoPE on Q and K
    int total_pairs = MROWS * NH * (HDIM / 2) + MROWS * NKV * (HDIM / 2);
    rope_kernel<<<(total_pairs + 255) / 256, 256>>>(Qp, Kp, fc);

    // Flash attention
    cudaFuncSetAttribute(flash_kernel, cudaFuncAttributeMaxDynamicSharedMemorySize,
                         FL_SMEM_BYTES);
    flash_kernel<<<dim3(TT / 64, BSZ * NH), blk, FL_SMEM_BYTES>>>(Qp, Kp, Vp, Yp);

    // Split Y and do output projection (tensor cores)
    split_kernel<<<(xn4 + 255) / 256, blk>>>(Yp, yh, yl, xn4);
    bgemm128<<<dim3(CC / 128, MROWS / 128), blk>>>(yh, yl, woh, wol, out, CC, CC);
}